// round 16
// baseline (speedup 1.0000x reference)
#include <cuda_runtime.h>
#include <cstdint>

// GraphAttention restructured (R15 = R13 + prep-on-s1 + MLP-4 A-gather in the
// edge epilogue; R14 double-buffering reverted as a measured regression):
//   A  = relu(srcF@src_w+src_b) @ W1[0:128]            (fused2_pair)
//   dstEnc = relu(dstF@dst_w+dst_b); C = dstEnc@W1[256:384] + b1  (fused2_pair)
//   edges counting-sorted by dst (int2); PERSISTENT edge kernel, warp tile
//   M=32 x N=64, run-merged red.global.v4 epilogue with batched A loads.
//   out = relu( relu(LN(H@W2 + dstEnc + deg*b2)) @ out_w + out_b + dstF )
// NOTE: tcgen05 unavailable (harness emits compute_103 PTX, not 103a).

#define S_N 16384
#define D_N 16384
#define F   128
#define PADH 68
#define HSTR 132
#define E_MAX (1 << 20)

__device__ float g_dst_enc[D_N * F];
__device__ float g_Aproj[S_N * F];
__device__ float g_Cproj[D_N * F];
__device__ float g_H[D_N * F];
__device__ int   g_deg[D_N];
__device__ int   g_cur[D_N];
__device__ int2  g_sedge[E_MAX];
__device__ uint32_t g_W1frag[16384];

// ---------------- tf32 helpers ----------------
__device__ __forceinline__ uint32_t f2tf32(float x) {
    uint32_t r;
    asm("cvt.rna.tf32.f32 %0, %1;" : "=r"(r) : "f"(x));
    return r;
}

__device__ __forceinline__ void mma_tf32(float c[4], uint32_t a0, uint32_t a1,
                                         uint32_t a2, uint32_t a3,
                                         uint32_t b0, uint32_t b1) {
    asm volatile(
        "mma.sync.aligned.m16n8k8.row.col.f32.tf32.tf32.f32 "
        "{%0,%1,%2,%3}, {%4,%5,%6,%7}, {%8,%9}, {%0,%1,%2,%3};"
        : "+f"(c[0]), "+f"(c[1]), "+f"(c[2]), "+f"(c[3])
        : "r"(a0), "r"(a1), "r"(a2), "r"(a3), "r"(b0), "r"(b1));
}

__device__ __forceinline__ void red4(float* p, float4 v) {
    asm volatile("red.global.add.v4.f32 [%0], {%1,%2,%3,%4};"
                 :: "l"(p), "f"(v.x), "f"(v.y), "f"(v.z), "f"(v.w) : "memory");
}

// ---------------- sort-by-dst kernels (4 edges/thread) ----------------
extern "C" __global__ void count_deg(const int* __restrict__ edst,
                                     int* __restrict__ deg, int E) {
    int e0 = (blockIdx.x * 256 + threadIdx.x) * 4;
#pragma unroll
    for (int i = 0; i < 4; i++) {
        int e = e0 + i;
        if (e < E) atomicAdd(&deg[edst[e]], 1);
    }
}

extern "C" __global__ void scan_cursors(const int* __restrict__ deg,
                                        int* __restrict__ cur) {
    __shared__ int warpsum[8];
    int t = threadIdx.x;
    int base = t * 64;
    int s = 0;
    for (int i = 0; i < 64; i++) s += deg[base + i];
    int lane = t & 31, w = t >> 5;
    int v = s;
#pragma unroll
    for (int o = 1; o < 32; o <<= 1) {
        int u = __shfl_up_sync(0xffffffffu, v, o);
        if (lane >= o) v += u;
    }
    if (lane == 31) warpsum[w] = v;
    __syncthreads();
    if (t == 0) {
        int run = 0;
        for (int j = 0; j < 8; j++) { int tmp = warpsum[j]; warpsum[j] = run; run += tmp; }
    }
    __syncthreads();
    int run = v - s + warpsum[w];
    for (int i = 0; i < 64; i++) { cur[base + i] = run; run += deg[base + i]; }
}

extern "C" __global__ void scatter_sort(const int* __restrict__ esrc,
                                        const int* __restrict__ edst,
                                        int* __restrict__ cur,
                                        int2* __restrict__ sedge, int E) {
    int e0 = (blockIdx.x * 256 + threadIdx.x) * 4;
    int ss[4], dd[4];
#pragma unroll
    for (int i = 0; i < 4; i++) {
        int e = e0 + i;
        if (e < E) { ss[i] = esrc[e]; dd[i] = edst[e]; } else dd[i] = -1;
    }
#pragma unroll
    for (int i = 0; i < 4; i++) {
        if (dd[i] >= 0) {
            int pos = atomicAdd(&cur[dd[i]], 1);
            sedge[pos] = make_int2(ss[i], dd[i]);
        }
    }
}

// ---------------- W1b fragment precompute ----------------
extern "C" __global__ void prep_w1b(const float* __restrict__ W1b,
                                    uint32_t* __restrict__ frag) {
    int p = blockIdx.x * 256 + threadIdx.x;   // 16384
    int kc = p >> 7, n = p & 127;
    const float* bp = W1b + (size_t)(kc * 8) * 128 + n;
#pragma unroll
    for (int j = 0; j < 8; j++)
        frag[p * 8 + j] = f2tf32(bp[(((j & 1) << 2) + (j >> 1)) * 128]);
}

// ---------------- fused 2-stage node GEMM body ----------------
__device__ __forceinline__ void stage_B_frag(const float* __restrict__ B,
                                             uint32_t* __restrict__ Bs, int tid) {
    for (int i = 0; i < 8; i++) {
        int p = tid + i * 256;
        int kc = p >> 7, n = p & 127;
        const float* bp = B + (size_t)(kc * 8) * 128 + n;
        uint32_t v[8];
#pragma unroll
        for (int j = 0; j < 8; j++)
            v[j] = f2tf32(bp[(((j & 1) << 2) + (j >> 1)) * 128]);
        uint4* d = reinterpret_cast<uint4*>(Bs + p * 8);
        d[0] = make_uint4(v[0], v[1], v[2], v[3]);
        d[1] = make_uint4(v[4], v[5], v[6], v[7]);
    }
}

__device__ __forceinline__ void mainloop_tc(const float* __restrict__ buf0,
                                            const float* __restrict__ buf1,
                                            const uint32_t* __restrict__ Bs,
                                            float acc[2][8][4],
                                            int warp, int lane) {
    int g = lane >> 2, tig = lane & 3;
    int mrow = (warp & 3) * 32;
    int nbase = (warp >> 2) * 64;
    const uint2* B2p = reinterpret_cast<const uint2*>(Bs);
#pragma unroll
    for (int kc = 0; kc < 16; kc++) {
        const float* bh = (kc < 8) ? buf0 : buf1;
        int k0 = (kc & 7) * 8 + tig;
        uint32_t a[2][4];
#pragma unroll
        for (int mt = 0; mt < 2; mt++) {
            int r = mrow + mt * 16 + g;
            a[mt][0] = f2tf32(bh[r * PADH + k0]);
            a[mt][1] = f2tf32(bh[(r + 8) * PADH + k0]);
            a[mt][2] = f2tf32(bh[r * PADH + k0 + 4]);
            a[mt][3] = f2tf32(bh[(r + 8) * PADH + k0 + 4]);
        }
#pragma unroll
        for (int nt = 0; nt < 8; nt++) {
            int n = nbase + nt * 8 + g;
            uint2 bb = B2p[(kc * 128 + n) * 4 + tig];
            mma_tf32(acc[0][nt], a[0][0], a[0][1], a[0][2], a[0][3], bb.x, bb.y);
            mma_tf32(acc[1][nt], a[1][0], a[1][1], a[1][2], a[1][3], bb.x, bb.y);
        }
    }
}

__device__ __forceinline__ void fused2_body(
       const float* __restrict__ X, const float* __restrict__ B1,
       const float* __restrict__ bias1, const float* __restrict__ add1,
       const int* __restrict__ deg, const float* __restrict__ degv,
       int relu1, float* __restrict__ wS1,
       int do_ln, const float* __restrict__ lng, const float* __restrict__ lnb,
       const float* __restrict__ B2, const float* __restrict__ bias2,
       const float* __restrict__ add2, int relu2, float* __restrict__ out,
       int row0, float* sm) {
    float* buf0 = sm;
    float* buf1 = sm + 128 * PADH;
    uint32_t* Bs = reinterpret_cast<uint32_t*>(sm + 2 * 128 * PADH);

    int tid = threadIdx.x;
    int lane = tid & 31, warp = tid >> 5;

    {
        const float* Xp = X + (size_t)row0 * 128;
        for (int i = 0; i < 16; i++) {
            int idx = tid + i * 256;
            int row = idx >> 5, q = idx & 31;
            float4 v = *reinterpret_cast<const float4*>(Xp + (size_t)row * 128 + q * 4);
            float* d = (q < 16 ? buf0 : buf1) + row * PADH + (q & 15) * 4;
            *reinterpret_cast<float4*>(d) = v;
        }
    }
    stage_B_frag(B1, Bs, tid);
    __syncthreads();

    float acc[2][8][4];
#pragma unroll
    for (int mt = 0; mt < 2; mt++)
#pragma unroll
        for (int nt = 0; nt < 8; nt++)
#pragma unroll
            for (int j = 0; j < 4; j++) acc[mt][nt][j] = 0.f;

    mainloop_tc(buf0, buf1, Bs, acc, warp, lane);
    __syncthreads();

    {
        int g = lane >> 2, tig = lane & 3;
        int mrow = (warp & 3) * 32;
        int nbase = (warp >> 2) * 64;
#pragma unroll
        for (int mt = 0; mt < 2; mt++) {
#pragma unroll
            for (int nt = 0; nt < 8; nt++) {
                int col = nbase + nt * 8 + 2 * tig;
#pragma unroll
                for (int half = 0; half < 2; half++) {
                    int r = mrow + mt * 16 + g + half * 8;
                    float v0 = acc[mt][nt][half * 2];
                    float v1 = acc[mt][nt][half * 2 + 1];
                    if (bias1) { v0 += bias1[col]; v1 += bias1[col + 1]; }
                    if (add1) {
                        float2 av = *reinterpret_cast<const float2*>(
                            add1 + (size_t)(row0 + r) * 128 + col);
                        v0 += av.x; v1 += av.y;
                    }
                    if (deg) {
                        float dv = (float)deg[row0 + r];
                        v0 += dv * degv[col]; v1 += dv * degv[col + 1];
                    }
                    if (relu1) { v0 = fmaxf(v0, 0.f); v1 = fmaxf(v1, 0.f); }
                    float* bp = (col < 64 ? buf0 : buf1) + r * PADH + (col & 63);
                    bp[0] = v0; bp[1] = v1;
                    if (wS1) {
                        *reinterpret_cast<float2*>(wS1 + (size_t)(row0 + r) * 128 + col) =
                            make_float2(v0, v1);
                    }
                }
            }
        }
    }
    stage_B_frag(B2, Bs, tid);
    __syncthreads();

    if (do_ln) {
        int r = tid >> 1, h = tid & 1;
        float* bp = (h ? buf1 : buf0) + r * PADH;
        float s = 0.f;
#pragma unroll 8
        for (int j = 0; j < 64; j++) s += bp[j];
        s += __shfl_xor_sync(0xffffffffu, s, 1);
        float mu = s * (1.f / 128.f);
        float q = 0.f;
#pragma unroll 8
        for (int j = 0; j < 64; j++) { float d = bp[j] - mu; q += d * d; }
        q += __shfl_xor_sync(0xffffffffu, q, 1);
        float rs = rsqrtf(q * (1.f / 128.f) + 1e-5f);
#pragma unroll 8
        for (int j = 0; j < 64; j++) {
            int col = h * 64 + j;
            bp[j] = fmaxf(fmaf((bp[j] - mu) * rs, lng[col], lnb[col]), 0.f);
        }
        __syncthreads();
    }

#pragma unroll
    for (int mt = 0; mt < 2; mt++)
#pragma unroll
        for (int nt = 0; nt < 8; nt++)
#pragma unroll
            for (int j = 0; j < 4; j++) acc[mt][nt][j] = 0.f;

    mainloop_tc(buf0, buf1, Bs, acc, warp, lane);

    {
        int g = lane >> 2, tig = lane & 3;
        int mrow = (warp & 3) * 32;
        int nbase = (warp >> 2) * 64;
#pragma unroll
        for (int mt = 0; mt < 2; mt++) {
#pragma unroll
            for (int nt = 0; nt < 8; nt++) {
                int col = nbase + nt * 8 + 2 * tig;
#pragma unroll
                for (int half = 0; half < 2; half++) {
                    int r = mrow + mt * 16 + g + half * 8;
                    float v0 = acc[mt][nt][half * 2];
                    float v1 = acc[mt][nt][half * 2 + 1];
                    if (bias2) { v0 += bias2[col]; v1 += bias2[col + 1]; }
                    if (add2) {
                        float2 av = *reinterpret_cast<const float2*>(
                            add2 + (size_t)(row0 + r) * 128 + col);
                        v0 += av.x; v1 += av.y;
                    }
                    if (relu2) { v0 = fmaxf(v0, 0.f); v1 = fmaxf(v1, 0.f); }
                    *reinterpret_cast<float2*>(out + (size_t)(row0 + r) * 128 + col) =
                        make_float2(v0, v1);
                }
            }
        }
    }
}

extern "C" __global__ void __launch_bounds__(256, 1)
fused2(const float* __restrict__ X, const float* __restrict__ B1,
       const float* __restrict__ bias1, const float* __restrict__ add1,
       const int* __restrict__ deg, const float* __restrict__ degv,
       int relu1, float* __restrict__ wS1,
       int do_ln, const float* __restrict__ lng, const float* __restrict__ lnb,
       const float* __restrict__ B2, const float* __restrict__ bias2,
       const float* __restrict__ add2, int relu2, float* __restrict__ out) {
    extern __shared__ float sm[];
    fused2_body(X, B1, bias1, add1, deg, degv, relu1, wS1, do_ln, lng, lnb,
                B2, bias2, add2, relu2, out, blockIdx.x * 128, sm);
}

extern "C" __global__ void __launch_bounds__(256, 1)
fused2_pair(const float* __restrict__ srcF, const float* __restrict__ src_w,
            const float* __restrict__ src_b, const float* __restrict__ W1a,
            float* __restrict__ Aout,
            const float* __restrict__ dstF, const float* __restrict__ dst_w,
            const float* __restrict__ dst_b, float* __restrict__ dstEnc,
            const float* __restrict__ W1c, const float* __restrict__ b1,
            float* __restrict__ Cout) {
    extern __shared__ float sm[];
    int b = blockIdx.x;
    if (b < 128) {
        fused2_body(srcF, src_w, src_b, nullptr, nullptr, nullptr, 1, nullptr,
                    0, nullptr, nullptr, W1a, nullptr, nullptr, 0, Aout,
                    b * 128, sm);
    } else {
        fused2_body(dstF, dst_w, dst_b, nullptr, nullptr, nullptr, 1, dstEnc,
                    0, nullptr, nullptr, W1c, b1, nullptr, 0, Cout,
                    (b - 128) * 128, sm);
    }
}

// ---------------- persistent edge kernel (warp tile M=32 x N=64) -------------
// Epilogue A-gather batched 4 rows at a time (MLP=4) to break the per-row
// L2-latency chain.
extern "C" __global__ void __launch_bounds__(256, 2)
edge_kernel(const float* __restrict__ spos, const float* __restrict__ dpos,
            const int2* __restrict__ sedge,
            const float* __restrict__ distw, const float* __restrict__ distb,
            const uint32_t* __restrict__ W1frag,
            const float* __restrict__ Aproj, const float* __restrict__ Cproj,
            float* __restrict__ H, int E, int ntiles) {
    extern __shared__ uint32_t smu[];
    uint32_t* Bs  = smu;                                    // 16384 words
    float* hbuf = reinterpret_cast<float*>(smu + 16384);    // 64*HSTR floats
    float* w0r = hbuf + 64 * HSTR;                          // 128
    float* w1r = w0r + 128;
    float* br  = w1r + 128;
    float* dxs = br + 128;
    float* dys = dxs + 128;
    int*   sidx = (int*)(dys + 128);
    int*   didx = sidx + 128;

    int tid = threadIdx.x, lane = tid & 31, warp = tid >> 5;
    int g = lane >> 2, tig = lane & 3;
    int wm = warp & 3, wn = warp >> 2;

    {
        const uint4* s4 = reinterpret_cast<const uint4*>(W1frag);
        uint4* d4 = reinterpret_cast<uint4*>(Bs);
        for (int i = tid; i < 4096; i += 256) d4[i] = s4[i];
        if (tid < 128) {
            w0r[tid] = distw[tid];
            w1r[tid] = distw[128 + tid];
            br[tid]  = distb[tid];
        }
    }

    const uint2* B2 = reinterpret_cast<const uint2*>(Bs);

    for (int tile = blockIdx.x; tile < ntiles; tile += gridDim.x) {
        if (tid < 128) {
            int e = tile * 128 + tid;
            if (e < E) {
                int2 sd = sedge[e];
                sidx[tid] = sd.x;
                didx[tid] = sd.y;
                float2 sp = *reinterpret_cast<const float2*>(spos + 2 * (size_t)sd.x);
                float2 dp = *reinterpret_cast<const float2*>(dpos + 2 * (size_t)sd.y);
                dxs[tid] = sp.x - dp.x;
                dys[tid] = sp.y - dp.y;
            } else {
                sidx[tid] = 0; didx[tid] = -1;
                dxs[tid] = 0.f; dys[tid] = 0.f;
            }
        }
        __syncthreads();

        float dxa[4], dya[4];
#pragma unroll
        for (int q = 0; q < 4; q++) {
            dxa[q] = dxs[wm * 32 + q * 8 + g];
            dya[q] = dys[wm * 32 + q * 8 + g];
        }

        float acc[2][8][4];
#pragma unroll
        for (int mt = 0; mt < 2; mt++)
#pragma unroll
            for (int nt = 0; nt < 8; nt++)
#pragma unroll
                for (int j = 0; j < 4; j++) acc[mt][nt][j] = 0.f;

#pragma unroll
        for (int kc = 0; kc < 16; kc++) {
            int k0 = kc * 8 + tig;
            float w00 = w0r[k0], w10 = w1r[k0], bb0 = br[k0];
            float w01 = w0r[k0 + 4], w11 = w1r[k0 + 4], bb1 = br[k0 + 4];
            uint32_t a[2][4];
#pragma unroll
            for (int mt = 0; mt < 2; mt++) {
                a[mt][0] = f2tf32(fmaxf(fmaf(dxa[2*mt],   w00, fmaf(dya[2*mt],   w10, bb0)), 0.f));
                a[mt][1] = f2tf32(fmaxf(fmaf(dxa[2*mt+1], w00, fmaf(dya[2*mt+1], w10, bb0)), 0.f));
                a[mt][2] = f2tf32(fmaxf(fmaf(dxa[2*mt],   w01, fmaf(dya[2*mt],   w11, bb1)), 0.f));
                a[mt][3] = f2tf32(fmaxf(fmaf(dxa[2*mt+1], w01, fmaf(dya[2*mt+1], w11, bb1)), 0.f));
            }
#pragma unroll
            for (int nt = 0; nt < 8; nt++) {
                uint2 bb = B2[(kc * 128 + wn * 64 + nt * 8 + g) * 4 + tig];
                mma_tf32(acc[0][nt], a[0][0], a[0][1], a[0][2], a[0][3], bb.x, bb.y);
                mma_tf32(acc[1][nt], a[1][0], a[1][1], a[1][2], a[1][3], bb.x, bb.y);
            }
        }

#pragma unroll
        for (int c = 0; c < 2; c++) {
            if ((wm >> 1) == c) {
                int rbase = (wm & 1) * 32;
#pragma unroll
                for (int mt = 0; mt < 2; mt++)
#pragma unroll
                    for (int nt = 0; nt < 8; nt++) {
                        int col = wn * 64 + nt * 8 + tig * 2;
                        int r = rbase + mt * 16 + g;
                        *reinterpret_cast<float2*>(hbuf + r * HSTR + col) =
                            make_float2(acc[mt][nt][0], acc[mt][nt][1]);
                        *reinterpret_cast<float2*>(hbuf + (r + 8) * HSTR + col) =
                            make_float2(acc[mt][nt][2], acc[mt][nt][3]);
                    }
            }
            __syncthreads();

            // run-merged reduce; A rows loaded 4-at-a-time (MLP=4)
            {
                int lr0 = warp * 8;
                int cur_d = -2;
                float4 acc4 = make_float4(0.f, 0.f, 0.f, 0.f);
                float4 C4   = make_float4(0.f, 0.f, 0.f, 0.f);
#pragma unroll
                for (int half = 0; half < 2; half++) {
                    float4 Arow[4];
#pragma unroll
                    for (int r4 = 0; r4 < 4; r4++) {
                        int gi = c * 64 + lr0 + half * 4 + r4;
                        Arow[r4] = reinterpret_cast<const float4*>(
                            Aproj + (size_t)sidx[gi] * 128)[lane];
                    }
#pragma unroll
                    for (int r4 = 0; r4 < 4; r4++) {
                        int gi = c * 64 + lr0 + half * 4 + r4;
                        int d = didx[gi];
                        if (d != cur_d) {
                            if (cur_d >= 0)
                                red4(H + (size_t)cur_d * 128 + lane * 4, acc4);
                            cur_d = d;
                            acc4 = make_float4(0.f, 0.f, 0.f, 0.f);
                            if (d >= 0)
                                C4 = reinterpret_cast<const float4*>(
                                    Cproj + (size_t)d * 128)[lane];
                        }
                        if (d < 0) continue;
                        const float* hr = hbuf + (lr0 + half * 4 + r4) * HSTR + lane * 4;
                        acc4.x += fmaxf(hr[0] + Arow[r4].x + C4.x, 0.f);
                        acc4.y += fmaxf(hr[1] + Arow[r4].y + C4.y, 0.f);
                        acc4.z += fmaxf(hr[2] + Arow[r4].z + C4.z, 0.f);
                        acc4.w += fmaxf(hr[3] + Arow[r4].w + C4.w, 0.f);
                    }
                }
                if (cur_d >= 0)
                    red4(H + (size_t)cur_d * 128 + lane * 4, acc4);
            }
            __syncthreads();
        }
    }
}

// ---------------- launch ----------------
extern "C" void kernel_launch(void* const* d_in, const int* in_sizes, int n_in,
                              void* d_out, int out_size) {
    const float* srcF   = (const float*)d_in[0];
    const float* spos   = (const float*)d_in[1];
    const float* dstF   = (const float*)d_in[2];
    const float* dpos   = (const float*)d_in[3];
    const float* src_w  = (const float*)d_in[4];
    const float* src_b  = (const float*)d_in[5];
    const float* dst_w  = (const float*)d_in[6];
    const float* dst_b  = (const float*)d_in[7];
    const float* dist_w = (const float*)d_in[8];
    const float* dist_b = (const float*)d_in[9];
    const float* w1     = (const float*)d_in[10];
    const float* b1     = (const float*)d_in[11];
    const float* w2     = (const float*)d_in[12];
    const float* b2     = (const float*)d_in[13];
    const float* lng    = (const float*)d_in[14];
    const float* lnb    = (const float*)d_in[15];
    const float* out_w  = (const float*)d_in[16];
    const float* out_b  = (const float*)d_in[17];
    const int*   esrc   = (const int*)d_in[18];
    const int*   edst   = (const int*)d_in[19];
    int E = in_sizes[18];
    float* out = (float*)d_out;

    float *pDstEnc, *pA, *pC, *pH;
    int *pDeg, *pCur;
    int2* pSedge;
    uint32_t* pW1f;
    cudaGetSymbolAddress((void**)&pDstEnc, g_dst_enc);
    cudaGetSymbolAddress((void**)&pA, g_Aproj);
    cudaGetSymbolAddress((void**)&pC, g_Cproj);
    cudaGetSymbolAddress((void**)&pH, g_H);
    cudaGetSymbolAddress((void**)&pDeg, g_deg);
    cudaGetSymbolAddress((void**)&pCur, g_cur);
    cudaGetSymbolAddress((void**)&pSedge, g_sedge);
    cudaGetSymbolAddress((void**)&pW1f, g_W1frag);

    const int SMEM_F = (2 * 128 * PADH) * 4 + 16384 * 4;              // 135168 B
    const int SMEM_E = (16384 + 64 * HSTR + 7 * 128) * 4;             // 102912 B
    cudaFuncSetAttribute(fused2, cudaFuncAttributeMaxDynamicSharedMemorySize, SMEM_F);
    cudaFuncSetAttribute(fused2_pair, cudaFuncAttributeMaxDynamicSharedMemorySize, SMEM_F);
    cudaFuncSetAttribute(edge_kernel, cudaFuncAttributeMaxDynamicSharedMemorySize, SMEM_E);

    // fork: prep + sort chain on s1, node GEMMs on main stream
    cudaStream_t s1;
    cudaStreamCreateWithFlags(&s1, cudaStreamNonBlocking);
    cudaEvent_t evFork, evJoin;
    cudaEventCreateWithFlags(&evFork, cudaEventDisableTiming);
    cudaEventCreateWithFlags(&evJoin, cudaEventDisableTiming);

    cudaEventRecord(evFork, 0);
    cudaStreamWaitEvent(s1, evFork, 0);

    // --- s1: W1b prep + counting sort by dst ---
    prep_w1b<<<64, 256, 0, s1>>>(w1 + 128 * 128, pW1f);
    cudaMemsetAsync(pDeg, 0, (size_t)D_N * sizeof(int), s1);
    int nbE4 = (E + 1023) / 1024;
    count_deg<<<nbE4, 256, 0, s1>>>(edst, pDeg, E);
    scan_cursors<<<1, 256, 0, s1>>>(pDeg, pCur);
    scatter_sort<<<nbE4, 256, 0, s1>>>(esrc, edst, pCur, pSedge, E);
    cudaEventRecord(evJoin, s1);

    // --- main: H clear + node GEMMs ---
    cudaMemsetAsync(pH, 0, (size_t)D_N * F * sizeof(float));
    fused2_pair<<<256, 256, SMEM_F>>>(srcF, src_w, src_b, w1, pA,
                                      dstF, dst_w, dst_b, pDstEnc,
                                      w1 + 256 * 128, b1, pC);

    // join, then edge + tail
    cudaStreamWaitEvent(0, evJoin, 0);
    int ntiles = (E + 127) / 128;
    edge_kernel<<<304, 256, SMEM_E>>>(spos, dpos, pSedge, dist_w, dist_b,
                                      pW1f, pA, pC, pH, E, ntiles);

    fused2<<<128, 256, SMEM_F>>>(pH, w2, nullptr, pDstEnc, pDeg, b2,
                                 0, nullptr, 1, lng, lnb,
                                 out_w, out_b, dstF, 1, out);
}

// round 17
// speedup vs baseline: 1.1575x; 1.1575x over previous
#include <cuda_runtime.h>
#include <cuda_bf16.h>
#include <cstdint>

// GraphAttention restructured (R16 = R13 + bf16 edge mainloop):
//   A  = relu(srcF@src_w+src_b) @ W1[0:128]            (fused2_pair, tf32)
//   dstEnc = relu(dstF@dst_w+dst_b); C = dstEnc@W1[256:384] + b1  (fused2_pair)
//   edges counting-sorted by dst (int2); PERSISTENT edge kernel, warp tile
//   M=32 x N=64 on mma.m16n8k16.bf16 (half the mma issues + half the B LDS
//   traffic of the tf32-k8 version), run-merged red.global.v4 epilogue (R13).
//   out = relu( relu(LN(H@W2 + dstEnc + deg*b2)) @ out_w + out_b + dstF )
// NOTE: tcgen05 unavailable (harness emits compute_103 PTX, not 103a).

#define S_N 16384
#define D_N 16384
#define F   128
#define PADH 68
#define HSTR 132
#define E_MAX (1 << 20)

__device__ float g_dst_enc[D_N * F];
__device__ float g_Aproj[S_N * F];
__device__ float g_Cproj[D_N * F];
__device__ float g_H[D_N * F];
__device__ int   g_deg[D_N];
__device__ int   g_cur[D_N];
__device__ int2  g_sedge[E_MAX];
__device__ uint2 g_W1bf[4096];   // bf16 W1b fragment: [(kc*128+n)*4+tig]

// ---------------- helpers ----------------
__device__ __forceinline__ uint32_t f2tf32(float x) {
    uint32_t r;
    asm("cvt.rna.tf32.f32 %0, %1;" : "=r"(r) : "f"(x));
    return r;
}

__device__ __forceinline__ uint32_t pack_bf16x2(float lo, float hi) {
    __nv_bfloat162 v = __floats2bfloat162_rn(lo, hi);
    return *reinterpret_cast<uint32_t*>(&v);
}

__device__ __forceinline__ void mma_tf32(float c[4], uint32_t a0, uint32_t a1,
                                         uint32_t a2, uint32_t a3,
                                         uint32_t b0, uint32_t b1) {
    asm volatile(
        "mma.sync.aligned.m16n8k8.row.col.f32.tf32.tf32.f32 "
        "{%0,%1,%2,%3}, {%4,%5,%6,%7}, {%8,%9}, {%0,%1,%2,%3};"
        : "+f"(c[0]), "+f"(c[1]), "+f"(c[2]), "+f"(c[3])
        : "r"(a0), "r"(a1), "r"(a2), "r"(a3), "r"(b0), "r"(b1));
}

__device__ __forceinline__ void mma_bf16(float c[4], uint32_t a0, uint32_t a1,
                                         uint32_t a2, uint32_t a3,
                                         uint32_t b0, uint32_t b1) {
    asm volatile(
        "mma.sync.aligned.m16n8k16.row.col.f32.bf16.bf16.f32 "
        "{%0,%1,%2,%3}, {%4,%5,%6,%7}, {%8,%9}, {%0,%1,%2,%3};"
        : "+f"(c[0]), "+f"(c[1]), "+f"(c[2]), "+f"(c[3])
        : "r"(a0), "r"(a1), "r"(a2), "r"(a3), "r"(b0), "r"(b1));
}

__device__ __forceinline__ void red4(float* p, float4 v) {
    asm volatile("red.global.add.v4.f32 [%0], {%1,%2,%3,%4};"
                 :: "l"(p), "f"(v.x), "f"(v.y), "f"(v.z), "f"(v.w) : "memory");
}

// ---------------- sort-by-dst kernels (4 edges/thread) ----------------
extern "C" __global__ void count_deg(const int* __restrict__ edst,
                                     int* __restrict__ deg, int E) {
    int e0 = (blockIdx.x * 256 + threadIdx.x) * 4;
#pragma unroll
    for (int i = 0; i < 4; i++) {
        int e = e0 + i;
        if (e < E) atomicAdd(&deg[edst[e]], 1);
    }
}

extern "C" __global__ void scan_cursors(const int* __restrict__ deg,
                                        int* __restrict__ cur) {
    __shared__ int warpsum[8];
    int t = threadIdx.x;
    int base = t * 64;
    int s = 0;
    for (int i = 0; i < 64; i++) s += deg[base + i];
    int lane = t & 31, w = t >> 5;
    int v = s;
#pragma unroll
    for (int o = 1; o < 32; o <<= 1) {
        int u = __shfl_up_sync(0xffffffffu, v, o);
        if (lane >= o) v += u;
    }
    if (lane == 31) warpsum[w] = v;
    __syncthreads();
    if (t == 0) {
        int run = 0;
        for (int j = 0; j < 8; j++) { int tmp = warpsum[j]; warpsum[j] = run; run += tmp; }
    }
    __syncthreads();
    int run = v - s + warpsum[w];
    for (int i = 0; i < 64; i++) { cur[base + i] = run; run += deg[base + i]; }
}

extern "C" __global__ void scatter_sort(const int* __restrict__ esrc,
                                        const int* __restrict__ edst,
                                        int* __restrict__ cur,
                                        int2* __restrict__ sedge, int E) {
    int e0 = (blockIdx.x * 256 + threadIdx.x) * 4;
    int ss[4], dd[4];
#pragma unroll
    for (int i = 0; i < 4; i++) {
        int e = e0 + i;
        if (e < E) { ss[i] = esrc[e]; dd[i] = edst[e]; } else dd[i] = -1;
    }
#pragma unroll
    for (int i = 0; i < 4; i++) {
        if (dd[i] >= 0) {
            int pos = atomicAdd(&cur[dd[i]], 1);
            sedge[pos] = make_int2(ss[i], dd[i]);
        }
    }
}

// ---------------- W1b bf16 fragment precompute ----------------
// entry p = kc*512 + n*4 + tig : uint2{ bf16x2(k0,k0+1), bf16x2(k0+8,k0+9) },
// k0 = kc*16 + 2*tig, column n.
extern "C" __global__ void prep_w1b_bf16(const float* __restrict__ W1b,
                                         uint2* __restrict__ frag) {
    int p = blockIdx.x * 256 + threadIdx.x;   // 4096 total
    int kc = p >> 9;
    int rem = p & 511;
    int n = rem >> 2, tig = rem & 3;
    int k0 = kc * 16 + 2 * tig;
    uint2 v;
    v.x = pack_bf16x2(W1b[(size_t)k0 * 128 + n],      W1b[(size_t)(k0 + 1) * 128 + n]);
    v.y = pack_bf16x2(W1b[(size_t)(k0 + 8) * 128 + n], W1b[(size_t)(k0 + 9) * 128 + n]);
    frag[p] = v;
}

// ---------------- fused 2-stage node GEMM (tf32, unchanged) ----------------
__device__ __forceinline__ void stage_B_frag(const float* __restrict__ B,
                                             uint32_t* __restrict__ Bs, int tid) {
    for (int i = 0; i < 8; i++) {
        int p = tid + i * 256;
        int kc = p >> 7, n = p & 127;
        const float* bp = B + (size_t)(kc * 8) * 128 + n;
        uint32_t v[8];
#pragma unroll
        for (int j = 0; j < 8; j++)
            v[j] = f2tf32(bp[(((j & 1) << 2) + (j >> 1)) * 128]);
        uint4* d = reinterpret_cast<uint4*>(Bs + p * 8);
        d[0] = make_uint4(v[0], v[1], v[2], v[3]);
        d[1] = make_uint4(v[4], v[5], v[6], v[7]);
    }
}

__device__ __forceinline__ void mainloop_tc(const float* __restrict__ buf0,
                                            const float* __restrict__ buf1,
                                            const uint32_t* __restrict__ Bs,
                                            float acc[2][8][4],
                                            int warp, int lane) {
    int g = lane >> 2, tig = lane & 3;
    int mrow = (warp & 3) * 32;
    int nbase = (warp >> 2) * 64;
    const uint2* B2p = reinterpret_cast<const uint2*>(Bs);
#pragma unroll
    for (int kc = 0; kc < 16; kc++) {
        const float* bh = (kc < 8) ? buf0 : buf1;
        int k0 = (kc & 7) * 8 + tig;
        uint32_t a[2][4];
#pragma unroll
        for (int mt = 0; mt < 2; mt++) {
            int r = mrow + mt * 16 + g;
            a[mt][0] = f2tf32(bh[r * PADH + k0]);
            a[mt][1] = f2tf32(bh[(r + 8) * PADH + k0]);
            a[mt][2] = f2tf32(bh[r * PADH + k0 + 4]);
            a[mt][3] = f2tf32(bh[(r + 8) * PADH + k0 + 4]);
        }
#pragma unroll
        for (int nt = 0; nt < 8; nt++) {
            int n = nbase + nt * 8 + g;
            uint2 bb = B2p[(kc * 128 + n) * 4 + tig];
            mma_tf32(acc[0][nt], a[0][0], a[0][1], a[0][2], a[0][3], bb.x, bb.y);
            mma_tf32(acc[1][nt], a[1][0], a[1][1], a[1][2], a[1][3], bb.x, bb.y);
        }
    }
}

__device__ __forceinline__ void fused2_body(
       const float* __restrict__ X, const float* __restrict__ B1,
       const float* __restrict__ bias1, const float* __restrict__ add1,
       const int* __restrict__ deg, const float* __restrict__ degv,
       int relu1, float* __restrict__ wS1,
       int do_ln, const float* __restrict__ lng, const float* __restrict__ lnb,
       const float* __restrict__ B2, const float* __restrict__ bias2,
       const float* __restrict__ add2, int relu2, float* __restrict__ out,
       int row0, float* sm) {
    float* buf0 = sm;
    float* buf1 = sm + 128 * PADH;
    uint32_t* Bs = reinterpret_cast<uint32_t*>(sm + 2 * 128 * PADH);

    int tid = threadIdx.x;
    int lane = tid & 31, warp = tid >> 5;

    {
        const float* Xp = X + (size_t)row0 * 128;
        for (int i = 0; i < 16; i++) {
            int idx = tid + i * 256;
            int row = idx >> 5, q = idx & 31;
            float4 v = *reinterpret_cast<const float4*>(Xp + (size_t)row * 128 + q * 4);
            float* d = (q < 16 ? buf0 : buf1) + row * PADH + (q & 15) * 4;
            *reinterpret_cast<float4*>(d) = v;
        }
    }
    stage_B_frag(B1, Bs, tid);
    __syncthreads();

    float acc[2][8][4];
#pragma unroll
    for (int mt = 0; mt < 2; mt++)
#pragma unroll
        for (int nt = 0; nt < 8; nt++)
#pragma unroll
            for (int j = 0; j < 4; j++) acc[mt][nt][j] = 0.f;

    mainloop_tc(buf0, buf1, Bs, acc, warp, lane);
    __syncthreads();

    {
        int g = lane >> 2, tig = lane & 3;
        int mrow = (warp & 3) * 32;
        int nbase = (warp >> 2) * 64;
#pragma unroll
        for (int mt = 0; mt < 2; mt++) {
#pragma unroll
            for (int nt = 0; nt < 8; nt++) {
                int col = nbase + nt * 8 + 2 * tig;
#pragma unroll
                for (int half = 0; half < 2; half++) {
                    int r = mrow + mt * 16 + g + half * 8;
                    float v0 = acc[mt][nt][half * 2];
                    float v1 = acc[mt][nt][half * 2 + 1];
                    if (bias1) { v0 += bias1[col]; v1 += bias1[col + 1]; }
                    if (add1) {
                        float2 av = *reinterpret_cast<const float2*>(
                            add1 + (size_t)(row0 + r) * 128 + col);
                        v0 += av.x; v1 += av.y;
                    }
                    if (deg) {
                        float dv = (float)deg[row0 + r];
                        v0 += dv * degv[col]; v1 += dv * degv[col + 1];
                    }
                    if (relu1) { v0 = fmaxf(v0, 0.f); v1 = fmaxf(v1, 0.f); }
                    float* bp = (col < 64 ? buf0 : buf1) + r * PADH + (col & 63);
                    bp[0] = v0; bp[1] = v1;
                    if (wS1) {
                        *reinterpret_cast<float2*>(wS1 + (size_t)(row0 + r) * 128 + col) =
                            make_float2(v0, v1);
                    }
                }
            }
        }
    }
    stage_B_frag(B2, Bs, tid);
    __syncthreads();

    if (do_ln) {
        int r = tid >> 1, h = tid & 1;
        float* bp = (h ? buf1 : buf0) + r * PADH;
        float s = 0.f;
#pragma unroll 8
        for (int j = 0; j < 64; j++) s += bp[j];
        s += __shfl_xor_sync(0xffffffffu, s, 1);
        float mu = s * (1.f / 128.f);
        float q = 0.f;
#pragma unroll 8
        for (int j = 0; j < 64; j++) { float d = bp[j] - mu; q += d * d; }
        q += __shfl_xor_sync(0xffffffffu, q, 1);
        float rs = rsqrtf(q * (1.f / 128.f) + 1e-5f);
#pragma unroll 8
        for (int j = 0; j < 64; j++) {
            int col = h * 64 + j;
            bp[j] = fmaxf(fmaf((bp[j] - mu) * rs, lng[col], lnb[col]), 0.f);
        }
        __syncthreads();
    }

#pragma unroll
    for (int mt = 0; mt < 2; mt++)
#pragma unroll
        for (int nt = 0; nt < 8; nt++)
#pragma unroll
            for (int j = 0; j < 4; j++) acc[mt][nt][j] = 0.f;

    mainloop_tc(buf0, buf1, Bs, acc, warp, lane);

    {
        int g = lane >> 2, tig = lane & 3;
        int mrow = (warp & 3) * 32;
        int nbase = (warp >> 2) * 64;
#pragma unroll
        for (int mt = 0; mt < 2; mt++) {
#pragma unroll
            for (int nt = 0; nt < 8; nt++) {
                int col = nbase + nt * 8 + 2 * tig;
#pragma unroll
                for (int half = 0; half < 2; half++) {
                    int r = mrow + mt * 16 + g + half * 8;
                    float v0 = acc[mt][nt][half * 2];
                    float v1 = acc[mt][nt][half * 2 + 1];
                    if (bias2) { v0 += bias2[col]; v1 += bias2[col + 1]; }
                    if (add2) {
                        float2 av = *reinterpret_cast<const float2*>(
                            add2 + (size_t)(row0 + r) * 128 + col);
                        v0 += av.x; v1 += av.y;
                    }
                    if (relu2) { v0 = fmaxf(v0, 0.f); v1 = fmaxf(v1, 0.f); }
                    *reinterpret_cast<float2*>(out + (size_t)(row0 + r) * 128 + col) =
                        make_float2(v0, v1);
                }
            }
        }
    }
}

extern "C" __global__ void __launch_bounds__(256, 1)
fused2(const float* __restrict__ X, const float* __restrict__ B1,
       const float* __restrict__ bias1, const float* __restrict__ add1,
       const int* __restrict__ deg, const float* __restrict__ degv,
       int relu1, float* __restrict__ wS1,
       int do_ln, const float* __restrict__ lng, const float* __restrict__ lnb,
       const float* __restrict__ B2, const float* __restrict__ bias2,
       const float* __restrict__ add2, int relu2, float* __restrict__ out) {
    extern __shared__ float sm[];
    fused2_body(X, B1, bias1, add1, deg, degv, relu1, wS1, do_ln, lng, lnb,
                B2, bias2, add2, relu2, out, blockIdx.x * 128, sm);
}

extern "C" __global__ void __launch_bounds__(256, 1)
fused2_pair(const float* __restrict__ srcF, const float* __restrict__ src_w,
            const float* __restrict__ src_b, const float* __restrict__ W1a,
            float* __restrict__ Aout,
            const float* __restrict__ dstF, const float* __restrict__ dst_w,
            const float* __restrict__ dst_b, float* __restrict__ dstEnc,
            const float* __restrict__ W1c, const float* __restrict__ b1,
            float* __restrict__ Cout) {
    extern __shared__ float sm[];
    int b = blockIdx.x;
    if (b < 128) {
        fused2_body(srcF, src_w, src_b, nullptr, nullptr, nullptr, 1, nullptr,
                    0, nullptr, nullptr, W1a, nullptr, nullptr, 0, Aout,
                    b * 128, sm);
    } else {
        fused2_body(dstF, dst_w, dst_b, nullptr, nullptr, nullptr, 1, dstEnc,
                    0, nullptr, nullptr, W1c, b1, nullptr, 0, Cout,
                    (b - 128) * 128, sm);
    }
}

// ---------------- persistent edge kernel (bf16 mainloop, R13 epilogue) ------
// Warp tile M=32 x N=64: wm = warp&3 -> rows, wn = warp>>2 -> cols.
// K=128 in 8 steps of k16. D fragment layout identical to tf32-k8 path.
extern "C" __global__ void __launch_bounds__(256, 2)
edge_kernel(const float* __restrict__ spos, const float* __restrict__ dpos,
            const int2* __restrict__ sedge,
            const float* __restrict__ distw, const float* __restrict__ distb,
            const uint2* __restrict__ W1bf,
            const float* __restrict__ Aproj, const float* __restrict__ Cproj,
            float* __restrict__ H, int E, int ntiles) {
    extern __shared__ uint32_t smu[];
    uint2* Bs   = reinterpret_cast<uint2*>(smu);            // 4096 uint2 = 32KB
    float* hbuf = reinterpret_cast<float*>(smu + 8192);     // 64*HSTR floats
    float* w0r = hbuf + 64 * HSTR;                          // 128
    float* w1r = w0r + 128;
    float* br  = w1r + 128;
    float* dxs = br + 128;
    float* dys = dxs + 128;
    int*   sidx = (int*)(dys + 128);
    int*   didx = sidx + 128;

    int tid = threadIdx.x, lane = tid & 31, warp = tid >> 5;
    int g = lane >> 2, tig = lane & 3;
    int wm = warp & 3, wn = warp >> 2;

    // persistent staging (once)
    {
        const uint4* s4 = reinterpret_cast<const uint4*>(W1bf);
        uint4* d4 = reinterpret_cast<uint4*>(Bs);
        for (int i = tid; i < 2048; i += 256) d4[i] = s4[i];
        if (tid < 128) {
            w0r[tid] = distw[tid];
            w1r[tid] = distw[128 + tid];
            br[tid]  = distb[tid];
        }
    }

    for (int tile = blockIdx.x; tile < ntiles; tile += gridDim.x) {
        if (tid < 128) {
            int e = tile * 128 + tid;
            if (e < E) {
                int2 sd = sedge[e];
                sidx[tid] = sd.x;
                didx[tid] = sd.y;
                float2 sp = *reinterpret_cast<const float2*>(spos + 2 * (size_t)sd.x);
                float2 dp = *reinterpret_cast<const float2*>(dpos + 2 * (size_t)sd.y);
                dxs[tid] = sp.x - dp.x;
                dys[tid] = sp.y - dp.y;
            } else {
                sidx[tid] = 0; didx[tid] = -1;
                dxs[tid] = 0.f; dys[tid] = 0.f;
            }
        }
        __syncthreads();

        float dxa[4], dya[4];   // [2*mt] = row wm*32+mt*16+g, [2*mt+1] = +8
#pragma unroll
        for (int q = 0; q < 4; q++) {
            int mt = q >> 1, hi = q & 1;
            dxa[q] = dxs[wm * 32 + mt * 16 + hi * 8 + g];
            dya[q] = dys[wm * 32 + mt * 16 + hi * 8 + g];
        }

        float acc[2][8][4];
#pragma unroll
        for (int mt = 0; mt < 2; mt++)
#pragma unroll
            for (int nt = 0; nt < 8; nt++)
#pragma unroll
                for (int j = 0; j < 4; j++) acc[mt][nt][j] = 0.f;

#pragma unroll
        for (int kc = 0; kc < 8; kc++) {
            int ka = kc * 16 + 2 * tig;   // ka, ka+1 ; kb = ka+8, ka+9
            float wa0x = w0r[ka],     wa0y = w1r[ka],     ba0 = br[ka];
            float wa1x = w0r[ka + 1], wa1y = w1r[ka + 1], ba1 = br[ka + 1];
            float wb0x = w0r[ka + 8], wb0y = w1r[ka + 8], bb0 = br[ka + 8];
            float wb1x = w0r[ka + 9], wb1y = w1r[ka + 9], bb1 = br[ka + 9];
            uint32_t a[2][4];
#pragma unroll
            for (int mt = 0; mt < 2; mt++) {
                float dx0 = dxa[2 * mt],     dy0 = dya[2 * mt];      // row g
                float dx1 = dxa[2 * mt + 1], dy1 = dya[2 * mt + 1];  // row g+8
                a[mt][0] = pack_bf16x2(
                    fmaxf(fmaf(dx0, wa0x, fmaf(dy0, wa0y, ba0)), 0.f),
                    fmaxf(fmaf(dx0, wa1x, fmaf(dy0, wa1y, ba1)), 0.f));
                a[mt][1] = pack_bf16x2(
                    fmaxf(fmaf(dx1, wa0x, fmaf(dy1, wa0y, ba0)), 0.f),
                    fmaxf(fmaf(dx1, wa1x, fmaf(dy1, wa1y, ba1)), 0.f));
                a[mt][2] = pack_bf16x2(
                    fmaxf(fmaf(dx0, wb0x, fmaf(dy0, wb0y, bb0)), 0.f),
                    fmaxf(fmaf(dx0, wb1x, fmaf(dy0, wb1y, bb1)), 0.f));
                a[mt][3] = pack_bf16x2(
                    fmaxf(fmaf(dx1, wb0x, fmaf(dy1, wb0y, bb0)), 0.f),
                    fmaxf(fmaf(dx1, wb1x, fmaf(dy1, wb1y, bb1)), 0.f));
            }
#pragma unroll
            for (int nt = 0; nt < 8; nt++) {
                uint2 bb = Bs[(kc * 128 + wn * 64 + nt * 8 + g) * 4 + tig];
                mma_bf16(acc[0][nt], a[0][0], a[0][1], a[0][2], a[0][3], bb.x, bb.y);
                mma_bf16(acc[1][nt], a[1][0], a[1][1], a[1][2], a[1][3], bb.x, bb.y);
            }
        }

        // two 64-row chunks: store -> run-merged reduce (R13 epilogue)
#pragma unroll
        for (int c = 0; c < 2; c++) {
            if ((wm >> 1) == c) {
                int rbase = (wm & 1) * 32;
#pragma unroll
                for (int mt = 0; mt < 2; mt++)
#pragma unroll
                    for (int nt = 0; nt < 8; nt++) {
                        int col = wn * 64 + nt * 8 + tig * 2;
                        int r = rbase + mt * 16 + g;
                        *reinterpret_cast<float2*>(hbuf + r * HSTR + col) =
                            make_float2(acc[mt][nt][0], acc[mt][nt][1]);
                        *reinterpret_cast<float2*>(hbuf + (r + 8) * HSTR + col) =
                            make_float2(acc[mt][nt][2], acc[mt][nt][3]);
                    }
            }
            __syncthreads();

            {
                int lr0 = warp * 8;
                int cur_d = -2;
                float4 acc4 = make_float4(0.f, 0.f, 0.f, 0.f);
                float4 C4   = make_float4(0.f, 0.f, 0.f, 0.f);
                float4 Anext = reinterpret_cast<const float4*>(
                    Aproj + (size_t)sidx[c * 64 + lr0] * 128)[lane];
#pragma unroll
                for (int r = 0; r < 8; r++) {
                    int gi = c * 64 + lr0 + r;
                    int d = didx[gi];
                    float4 Acur = Anext;
                    if (r < 7) {
                        Anext = reinterpret_cast<const float4*>(
                            Aproj + (size_t)sidx[gi + 1] * 128)[lane];
                    }
                    if (d != cur_d) {
                        if (cur_d >= 0)
                            red4(H + (size_t)cur_d * 128 + lane * 4, acc4);
                        cur_d = d;
                        acc4 = make_float4(0.f, 0.f, 0.f, 0.f);
                        if (d >= 0)
                            C4 = reinterpret_cast<const float4*>(
                                Cproj + (size_t)d * 128)[lane];
                    }
                    if (d < 0) continue;
                    const float* hr = hbuf + (lr0 + r) * HSTR + lane * 4;
                    acc4.x += fmaxf(hr[0] + Acur.x + C4.x, 0.f);
                    acc4.y += fmaxf(hr[1] + Acur.y + C4.y, 0.f);
                    acc4.z += fmaxf(hr[2] + Acur.z + C4.z, 0.f);
                    acc4.w += fmaxf(hr[3] + Acur.w + C4.w, 0.f);
                }
                if (cur_d >= 0)
                    red4(H + (size_t)cur_d * 128 + lane * 4, acc4);
            }
            __syncthreads();
        }
    }
}

// ---------------- launch ----------------
extern "C" void kernel_launch(void* const* d_in, const int* in_sizes, int n_in,
                              void* d_out, int out_size) {
    const float* srcF   = (const float*)d_in[0];
    const float* spos   = (const float*)d_in[1];
    const float* dstF   = (const float*)d_in[2];
    const float* dpos   = (const float*)d_in[3];
    const float* src_w  = (const float*)d_in[4];
    const float* src_b  = (const float*)d_in[5];
    const float* dst_w  = (const float*)d_in[6];
    const float* dst_b  = (const float*)d_in[7];
    const float* dist_w = (const float*)d_in[8];
    const float* dist_b = (const float*)d_in[9];
    const float* w1     = (const float*)d_in[10];
    const float* b1     = (const float*)d_in[11];
    const float* w2     = (const float*)d_in[12];
    const float* b2     = (const float*)d_in[13];
    const float* lng    = (const float*)d_in[14];
    const float* lnb    = (const float*)d_in[15];
    const float* out_w  = (const float*)d_in[16];
    const float* out_b  = (const float*)d_in[17];
    const int*   esrc   = (const int*)d_in[18];
    const int*   edst   = (const int*)d_in[19];
    int E = in_sizes[18];
    float* out = (float*)d_out;

    float *pDstEnc, *pA, *pC, *pH;
    int *pDeg, *pCur;
    int2* pSedge;
    uint2* pW1bf;
    cudaGetSymbolAddress((void**)&pDstEnc, g_dst_enc);
    cudaGetSymbolAddress((void**)&pA, g_Aproj);
    cudaGetSymbolAddress((void**)&pC, g_Cproj);
    cudaGetSymbolAddress((void**)&pH, g_H);
    cudaGetSymbolAddress((void**)&pDeg, g_deg);
    cudaGetSymbolAddress((void**)&pCur, g_cur);
    cudaGetSymbolAddress((void**)&pSedge, g_sedge);
    cudaGetSymbolAddress((void**)&pW1bf, g_W1bf);

    const int SMEM_F = (2 * 128 * PADH) * 4 + 16384 * 4;              // 135168 B
    const int SMEM_E = (8192 + 64 * HSTR + 7 * 128) * 4;              // 70144 B
    cudaFuncSetAttribute(fused2, cudaFuncAttributeMaxDynamicSharedMemorySize, SMEM_F);
    cudaFuncSetAttribute(fused2_pair, cudaFuncAttributeMaxDynamicSharedMemorySize, SMEM_F);
    cudaFuncSetAttribute(edge_kernel, cudaFuncAttributeMaxDynamicSharedMemorySize, SMEM_E);

    // fork: prep + sort chain on s1, node GEMMs on main stream
    cudaStream_t s1;
    cudaStreamCreateWithFlags(&s1, cudaStreamNonBlocking);
    cudaEvent_t evFork, evJoin;
    cudaEventCreateWithFlags(&evFork, cudaEventDisableTiming);
    cudaEventCreateWithFlags(&evJoin, cudaEventDisableTiming);

    cudaEventRecord(evFork, 0);
    cudaStreamWaitEvent(s1, evFork, 0);

    // --- s1: W1b bf16 prep + counting sort by dst ---
    prep_w1b_bf16<<<16, 256, 0, s1>>>(w1 + 128 * 128, pW1bf);
    cudaMemsetAsync(pDeg, 0, (size_t)D_N * sizeof(int), s1);
    int nbE4 = (E + 1023) / 1024;
    count_deg<<<nbE4, 256, 0, s1>>>(edst, pDeg, E);
    scan_cursors<<<1, 256, 0, s1>>>(pDeg, pCur);
    scatter_sort<<<nbE4, 256, 0, s1>>>(esrc, edst, pCur, pSedge, E);
    cudaEventRecord(evJoin, s1);

    // --- main: H clear + node GEMMs ---
    cudaMemsetAsync(pH, 0, (size_t)D_N * F * sizeof(float));
    fused2_pair<<<256, 256, SMEM_F>>>(srcF, src_w, src_b, w1, pA,
                                      dstF, dst_w, dst_b, pDstEnc,
                                      w1 + 256 * 128, b1, pC);

    // join, then edge + tail
    cudaStreamWaitEvent(0, evJoin, 0);
    int ntiles = (E + 127) / 128;
    edge_kernel<<<304, 256, SMEM_E>>>(spos, dpos, pSedge, dist_w, dist_b,
                                      pW1bf, pA, pC, pH, E, ntiles);

    fused2<<<128, 256, SMEM_F>>>(pH, w2, nullptr, pDstEnc, pDeg, b2,
                                 0, nullptr, 1, lng, lnb,
                                 out_w, out_b, dstF, 1, out);
}